// round 5
// baseline (speedup 1.0000x reference)
#include <cuda_runtime.h>
#include <math.h>

#define L_TOTAL 131072
#define NBATCH  8
#define CHUNK   32
#define FWARM   128
#define ENVW    384
#define SKEW    8
#define NCHUNK  (L_TOTAL / CHUNK)            // 4096
#define NPAIR   (NCHUNK / 2)                 // 2048 chunk-pairs
#define NTHREADS (NPAIR * NBATCH)            // 16384
#define BLOCK   128                          // 4 warps -> 1 per SMSP
#define ITERS   (CHUNK + FWARM + SKEW)       // 168
#define WSTART  (FWARM + SKEW)               // 136

__device__ __forceinline__ float ex2a(float x) {
    float y; asm("ex2.approx.ftz.f32 %0, %1;" : "=f"(y) : "f"(x)); return y;
}
__device__ __forceinline__ float rcpa(float x) {
    float y; asm("rcp.approx.ftz.f32 %0, %1;" : "=f"(y) : "f"(x)); return y;
}

struct Coef { float b0, b1, b2, a1, a2; };

// shared-coef biquad step, per-stream state passed by reference
__device__ __forceinline__ float bqstep(const Coef& c, float x, float& s1, float& s2) {
    float y = fmaf(c.b0, x, s1);
    float t = fmaf(c.b1, x, s2);
    s1 = fmaf(-c.a1, y, t);
    s2 = fmaf(-c.a2, y, c.b2 * x);
    return y;
}

__device__ __forceinline__ Coef mk_stable(float r0, float r1, float r2, float r3, float r4) {
    float a1 = 2.f * tanhf(r3);
    float aa = fabsf(a1);
    float a2 = 0.5f * fmaf(2.f - aa, tanhf(r4), aa);
    Coef c; c.b0 = r0; c.b1 = r1; c.b2 = r2; c.a1 = a1; c.a2 = a2;
    return c;
}

__global__ void __launch_bounds__(BLOCK, 1) amp_kernel(
    const float* __restrict__ X,     const float* __restrict__ knobs,
    const float* __restrict__ ecr,   const float* __restrict__ prep,
    const float* __restrict__ postp, const float* __restrict__ gwi,
    const float* __restrict__ gwh,   const float* __restrict__ gbi,
    const float* __restrict__ gbh,   const float* __restrict__ gow,
    const float* __restrict__ gob,   const float* __restrict__ sw1,
    const float* __restrict__ sb1,   const float* __restrict__ sw2,
    const float* __restrict__ sb2,   const float* __restrict__ fw1,
    const float* __restrict__ fb1,   const float* __restrict__ fw2,
    const float* __restrict__ fb2,   const float* __restrict__ famt,
    float* __restrict__ OUT)
{
    const int tid = blockIdx.x * BLOCK + threadIdx.x;
    if (tid >= NTHREADS) return;
    const int b  = tid & (NBATCH - 1);
    const int cp = tid >> 3;                  // 0..NPAIR-1

    // ---------------- shared (per-batch) setup ----------------
    const float cenv  = 1.f / (1.f + expf(-ecr[0]));
    const float ccenv = 1.f - cenv;

    const float k0 = knobs[b * 3 + 0];
    float acc = sb2[0];
#pragma unroll
    for (int j = 0; j < 8; j++) acc += sw2[j] * tanhf(fmaf(k0, sw1[j], sb1[j]));
    const float depth = 1.f / (1.f + expf(-acc));

    const Coef c1 = mk_stable(prep[0], prep[1], prep[2], prep[3], prep[4]);
    const Coef c2 = mk_stable(prep[5], prep[6], prep[7], prep[8], prep[9]);
    const Coef c3 = mk_stable(postp[0], postp[1], postp[2], postp[3], postp[4]);
    const Coef c4 = mk_stable(postp[5], postp[6], postp[7], postp[8], postp[9]);

    Coef cf;
    {
        const float k1 = knobs[b * 3 + 1], k2 = knobs[b * 3 + 2];
        float h16[16];
#pragma unroll
        for (int j = 0; j < 16; j++)
            h16[j] = tanhf(fmaf(k1, fw1[j * 2 + 0], fmaf(k2, fw1[j * 2 + 1], fb1[j])));
        float raw[5];
#pragma unroll
        for (int i = 0; i < 5; i++) {
            float a = fb2[i];
#pragma unroll
            for (int j = 0; j < 16; j++) a = fmaf(fw2[i * 16 + j], h16[j], a);
            raw[i] = a;
        }
        cf = mk_stable(raw[0], raw[1], raw[2], raw[3], raw[4]);
    }
    const float fbmix = 1.f / (1.f + expf(-famt[0]));

    // GRU constants (log2e folded)
    const float L2E = 1.4426950408889634f;
    const float NL2E = -2.f * L2E;
    const float ow = gow[0], ob = gob[0];
    const float rwx = -L2E * gwi[0], rwh = -L2E * gwh[0], rc = -L2E * (gbi[0] + gbh[0]);
    const float zwx = -L2E * gwi[1], zwh = -L2E * gwh[1], zc = -L2E * (gbi[1] + gbh[1]);
    const float wi2n = NL2E * gwi[2], bi2n = NL2E * gbi[2];
    const float wh2n = NL2E * gwh[2], bh2n = NL2E * gbh[2];

    const float* __restrict__ xr = X + (size_t)b * L_TOTAL;
    float* __restrict__ orow     = OUT + (size_t)b * L_TOTAL;

    // ---------------- two independent streams ----------------
    int   fb_[2], gg_[2];
    float env[2], hh[2];
    float d0[2], d1[2], d2[2], d3[2], d4[2], d5[2], d6[2], d7[2];
    float s11[2], s12[2], s21[2], s22[2], s31[2], s32[2], s41[2], s42[2], sf1[2], sf2[2];

#pragma unroll
    for (int k = 0; k < 2; k++) {
        const int c = cp + k * NPAIR;
        fb_[k] = c * CHUNK - FWARM;                 // may be negative (zero-padded)
        int g = 3 - fb_[k]; if (g < 3) g = 3;       // GRU start iteration
        gg_[k] = g;
        env[k] = 0.f; hh[k] = 0.f;
        d0[k]=d1[k]=d2[k]=d3[k]=d4[k]=d5[k]=d6[k]=d7[k]=0.f;
        s11[k]=s12[k]=s21[k]=s22[k]=s31[k]=s32[k]=s41[k]=s42[k]=sf1[k]=sf2[k]=0.f;
    }

    // ---------------- exact envelope pre-scan (zeros before t=0 are exact) ----------------
    {
        const float cc2 = cenv * cenv, cc4 = cc2 * cc2;
        const float g0 = ccenv * cenv * cc2;
        const float g1 = ccenv * cc2;
        const float g2 = ccenv * cenv;
        const float g3 = ccenv;
#pragma unroll
        for (int k = 0; k < 2; k++) {
            int t0 = fb_[k] - ENVW; if (t0 < 0) t0 = 0;
            float e = 0.f;
            for (int t = t0; t < fb_[k]; t += 4) {
                float4 v = *reinterpret_cast<const float4*>(xr + t);
                float a = g0 * fabsf(v.x);
                a = fmaf(g1, fabsf(v.y), a);
                a = fmaf(g2, fabsf(v.z), a);
                a = fmaf(g3, fabsf(v.w), a);
                e = fmaf(cc4, e, a);
            }
            env[k] = e;
        }
    }

    // ---------------- prologue: pipeline fill (scalar, guarded loads) ----------------
#pragma unroll
    for (int i = 0; i < SKEW; i++) {
#pragma unroll
        for (int k = 0; k < 2; k++) {
            float y1 = bqstep(c1, d0[k], s11[k], s12[k]);
            float y2 = bqstep(c2, d1[k], s21[k], s22[k]);
            float y3 = 0.f;
            if (i >= gg_[k]) {
                float er = ex2a(fmaf(hh[k], rwh, fmaf(d2[k], rwx, rc)));
                float ez = ex2a(fmaf(hh[k], zwh, fmaf(d2[k], zwx, zc)));
                float r = rcpa(1.f + er);
                float z = rcpa(1.f + ez);
                float gi2s = fmaf(d2[k], wi2n, bi2n);
                float gh2s = fmaf(hh[k], wh2n, bh2n);
                float en = ex2a(fmaf(r, gh2s, gi2s));
                float n = fmaf(2.f, rcpa(1.f + en), -1.f);
                hh[k] = fmaf(z, hh[k] - n, n);
                y3 = fmaf(hh[k], ow, ob);
            }
            float y4 = bqstep(c3, d3[k], s31[k], s32[k]);
            float y5 = bqstep(c4, d4[k], s41[k], s42[k]);
            int s = fb_[k] + i;
            float xv = (s >= 0 && s < L_TOTAL) ? xr[s] : 0.f;
            env[k] = fmaf(cenv, env[k], ccenv * fabsf(xv));
            float y0 = xv * fmaf(-depth, env[k], 1.f);
            d7[k]=d6[k]; d6[k]=d5[k]; d5[k]=y5; d4[k]=y4; d3[k]=y3; d2[k]=y2; d1[k]=y1; d0[k]=y0;
        }
    }

    // ---------------- main dual-stream skewed loop, 4-wide vector I/O ----------------
    for (int i = SKEW; i < ITERS; i += 4) {
        float xv4[2][4];
#pragma unroll
        for (int k = 0; k < 2; k++) {
            int s = fb_[k] + i;
            if (s >= 0 && s < L_TOTAL) {
                float4 v = *reinterpret_cast<const float4*>(xr + s);
                xv4[k][0]=v.x; xv4[k][1]=v.y; xv4[k][2]=v.z; xv4[k][3]=v.w;
            } else {
                xv4[k][0]=xv4[k][1]=xv4[k][2]=xv4[k][3]=0.f;
            }
        }

        float ov4[2][4];
#pragma unroll
        for (int j = 0; j < 4; j++) {
#pragma unroll
            for (int k = 0; k < 2; k++) {
                float xv = xv4[k][j];

                float y1 = bqstep(c1, d0[k], s11[k], s12[k]);
                float y2 = bqstep(c2, d1[k], s21[k], s22[k]);

                // GRU stage: chain from hh[k] ~92 cyc, interleaved with stream k^1
                float y3;
                if (i + j >= gg_[k]) {
                    float er = ex2a(fmaf(hh[k], rwh, fmaf(d2[k], rwx, rc)));
                    float ez = ex2a(fmaf(hh[k], zwh, fmaf(d2[k], zwx, zc)));
                    float r = rcpa(1.f + er);
                    float z = rcpa(1.f + ez);
                    float gi2s = fmaf(d2[k], wi2n, bi2n);
                    float gh2s = fmaf(hh[k], wh2n, bh2n);
                    float en = ex2a(fmaf(r, gh2s, gi2s));
                    float n = fmaf(2.f, rcpa(1.f + en), -1.f);
                    hh[k] = fmaf(z, hh[k] - n, n);
                    y3 = fmaf(hh[k], ow, ob);
                } else {
                    y3 = 0.f;
                }

                float y4 = bqstep(c3, d3[k], s31[k], s32[k]);
                float y5 = bqstep(c4, d4[k], s41[k], s42[k]);
                float yfb = bqstep(cf, d7[k], sf1[k], sf2[k]);
                ov4[k][j] = fmaf(-fbmix, yfb, d7[k]);

                env[k] = fmaf(cenv, env[k], ccenv * fabsf(xv));
                float y0 = xv * fmaf(-depth, env[k], 1.f);

                d7[k]=d6[k]; d6[k]=d5[k]; d5[k]=y5; d4[k]=y4; d3[k]=y3; d2[k]=y2; d1[k]=y1; d0[k]=y0;
            }
        }

        if (i >= WSTART) {
#pragma unroll
            for (int k = 0; k < 2; k++) {
                int s = fb_[k] + i;
                float4 o; o.x=ov4[k][0]; o.y=ov4[k][1]; o.z=ov4[k][2]; o.w=ov4[k][3];
                *reinterpret_cast<float4*>(orow + (s - SKEW)) = o;
            }
        }
    }
}

extern "C" void kernel_launch(void* const* d_in, const int* in_sizes, int n_in,
                              void* d_out, int out_size)
{
    const float* X     = (const float*)d_in[0];
    const float* knobs = (const float*)d_in[1];
    const float* ecr   = (const float*)d_in[2];
    const float* prep  = (const float*)d_in[3];
    const float* postp = (const float*)d_in[4];
    const float* gwi   = (const float*)d_in[5];
    const float* gwh   = (const float*)d_in[6];
    const float* gbi   = (const float*)d_in[7];
    const float* gbh   = (const float*)d_in[8];
    const float* gow   = (const float*)d_in[9];
    const float* gob   = (const float*)d_in[10];
    const float* sw1   = (const float*)d_in[11];
    const float* sb1   = (const float*)d_in[12];
    const float* sw2   = (const float*)d_in[13];
    const float* sb2   = (const float*)d_in[14];
    const float* fw1   = (const float*)d_in[15];
    const float* fb1   = (const float*)d_in[16];
    const float* fw2   = (const float*)d_in[17];
    const float* fb2   = (const float*)d_in[18];
    const float* famt  = (const float*)d_in[19];
    float* OUT = (float*)d_out;

    dim3 grid(NTHREADS / BLOCK);   // 128 blocks x 128 threads: 1 warp/SMSP, 2 streams/thread
    amp_kernel<<<grid, BLOCK>>>(X, knobs, ecr, prep, postp, gwi, gwh, gbi, gbh,
                                gow, gob, sw1, sb1, sw2, sb2, fw1, fb1, fw2, fb2,
                                famt, OUT);
}

// round 7
// speedup vs baseline: 2.2049x; 2.2049x over previous
#include <cuda_runtime.h>
#include <math.h>

#define L_TOTAL 131072
#define NBATCH  8
#define CHUNK   32
#define FWARM   128
#define ENVW    384
#define SKEW    8
#define NCHUNK  (L_TOTAL / CHUNK)            // 4096
#define NPAIR   (NCHUNK / 2)                 // 2048
#define NTHREADS (NPAIR * NBATCH)            // 16384
#define BLOCK   128                          // 1 warp per SMSP
#define ITERS   (CHUNK + FWARM + SKEW)       // 168
#define WSTART  (FWARM + SKEW)               // 136

__device__ __forceinline__ float ex2a(float x) {
    float y; asm("ex2.approx.ftz.f32 %0, %1;" : "=f"(y) : "f"(x)); return y;
}
__device__ __forceinline__ float rcpa(float x) {
    float y; asm("rcp.approx.ftz.f32 %0, %1;" : "=f"(y) : "f"(x)); return y;
}

struct Coef { float b0, b1, b2, a1, a2; };

__device__ __forceinline__ float bqstep(const Coef& c, float x, float& s1, float& s2) {
    float y = fmaf(c.b0, x, s1);
    float t = fmaf(c.b1, x, s2);
    s1 = fmaf(-c.a1, y, t);
    s2 = fmaf(-c.a2, y, c.b2 * x);
    return y;
}

__device__ __forceinline__ Coef mk_stable(float r0, float r1, float r2, float r3, float r4) {
    float a1 = 2.f * tanhf(r3);
    float aa = fabsf(a1);
    float a2 = 0.5f * fmaf(2.f - aa, tanhf(r4), aa);
    Coef c; c.b0 = r0; c.b1 = r1; c.b2 = r2; c.a1 = a1; c.a2 = a2;
    return c;
}

struct GruC {
    float rwx, rwh, rc, zwx, zwh, zc, wi2n, bi2n, wh2n, bh2n, ow, ob;
};

// One pipeline step for one stream. GUARDED enables the GRU-start select.
template<bool GUARDED>
__device__ __forceinline__ float pipe_step(
    float xv, int it, int gg,
    const Coef& c1, const Coef& c2, const Coef& c3, const Coef& c4, const Coef& cf,
    const GruC& G, float cenv, float ccenv, float depth, float fbmix,
    float& env, float& h,
    float& d0, float& d1, float& d2, float& d3,
    float& d4, float& d5, float& d6, float& d7,
    float& s11, float& s12, float& s21, float& s22,
    float& s31, float& s32, float& s41, float& s42,
    float& sf1, float& sf2)
{
    float y1 = bqstep(c1, d0, s11, s12);
    float y2 = bqstep(c2, d1, s21, s22);

    // GRU: chain h -> FFMA -> EX2 -> FADD -> RCP -> FFMA -> EX2 -> FADD -> RCP
    //      -> FFMA -> FADD -> FFMA (~92 cyc)
    float er = ex2a(fmaf(h, G.rwh, fmaf(d2, G.rwx, G.rc)));
    float ez = ex2a(fmaf(h, G.zwh, fmaf(d2, G.zwx, G.zc)));
    float r = rcpa(1.f + er);
    float z = rcpa(1.f + ez);
    float gi2s = fmaf(d2, G.wi2n, G.bi2n);
    float gh2s = fmaf(h, G.wh2n, G.bh2n);
    float en = ex2a(fmaf(r, gh2s, gi2s));
    float n = fmaf(2.f, rcpa(1.f + en), -1.f);
    float hn = fmaf(z, h - n, n);
    if (GUARDED) h = (it >= gg) ? hn : 0.f;   // predicated select, no branch
    else         h = hn;
    float y3 = fmaf(h, G.ow, G.ob);

    float y4 = bqstep(c3, d3, s31, s32);
    float y5 = bqstep(c4, d4, s41, s42);
    float yfb = bqstep(cf, d7, sf1, sf2);
    float ov = fmaf(-fbmix, yfb, d7);

    env = fmaf(cenv, env, ccenv * fabsf(xv));
    float y0 = xv * fmaf(-depth, env, 1.f);

    d7 = d6; d6 = d5; d5 = y5; d4 = y4; d3 = y3; d2 = y2; d1 = y1; d0 = y0;
    return ov;
}

__global__ void __launch_bounds__(BLOCK, 1) amp_kernel(
    const float* __restrict__ X,     const float* __restrict__ knobs,
    const float* __restrict__ ecr,   const float* __restrict__ prep,
    const float* __restrict__ postp, const float* __restrict__ gwi,
    const float* __restrict__ gwh,   const float* __restrict__ gbi,
    const float* __restrict__ gbh,   const float* __restrict__ gow,
    const float* __restrict__ gob,   const float* __restrict__ sw1,
    const float* __restrict__ sb1,   const float* __restrict__ sw2,
    const float* __restrict__ sb2,   const float* __restrict__ fw1,
    const float* __restrict__ fb1,   const float* __restrict__ fw2,
    const float* __restrict__ fb2,   const float* __restrict__ famt,
    float* __restrict__ OUT)
{
    const int tid = blockIdx.x * BLOCK + threadIdx.x;
    if (tid >= NTHREADS) return;
    const int b  = tid & (NBATCH - 1);
    const int cp = tid >> 3;

    // ---------------- per-batch setup ----------------
    const float cenv  = 1.f / (1.f + expf(-ecr[0]));
    const float ccenv = 1.f - cenv;

    const float k0 = knobs[b * 3 + 0];
    float acc = sb2[0];
#pragma unroll
    for (int j = 0; j < 8; j++) acc += sw2[j] * tanhf(fmaf(k0, sw1[j], sb1[j]));
    const float depth = 1.f / (1.f + expf(-acc));

    const Coef c1 = mk_stable(prep[0], prep[1], prep[2], prep[3], prep[4]);
    const Coef c2 = mk_stable(prep[5], prep[6], prep[7], prep[8], prep[9]);
    const Coef c3 = mk_stable(postp[0], postp[1], postp[2], postp[3], postp[4]);
    const Coef c4 = mk_stable(postp[5], postp[6], postp[7], postp[8], postp[9]);

    Coef cf;
    {
        const float k1 = knobs[b * 3 + 1], k2 = knobs[b * 3 + 2];
        float h16[16];
#pragma unroll
        for (int j = 0; j < 16; j++)
            h16[j] = tanhf(fmaf(k1, fw1[j * 2 + 0], fmaf(k2, fw1[j * 2 + 1], fb1[j])));
        float raw[5];
#pragma unroll
        for (int i = 0; i < 5; i++) {
            float a = fb2[i];
#pragma unroll
            for (int j = 0; j < 16; j++) a = fmaf(fw2[i * 16 + j], h16[j], a);
            raw[i] = a;
        }
        cf = mk_stable(raw[0], raw[1], raw[2], raw[3], raw[4]);
    }
    const float fbmix = 1.f / (1.f + expf(-famt[0]));

    const float L2E = 1.4426950408889634f;
    const float NL2E = -2.f * L2E;
    GruC G;
    G.rwx = -L2E * gwi[0]; G.rwh = -L2E * gwh[0]; G.rc = -L2E * (gbi[0] + gbh[0]);
    G.zwx = -L2E * gwi[1]; G.zwh = -L2E * gwh[1]; G.zc = -L2E * (gbi[1] + gbh[1]);
    G.wi2n = NL2E * gwi[2]; G.bi2n = NL2E * gbi[2];
    G.wh2n = NL2E * gwh[2]; G.bh2n = NL2E * gbh[2];
    G.ow = gow[0]; G.ob = gob[0];

    const float* __restrict__ xr = X + (size_t)b * L_TOTAL;
    float* __restrict__ orow     = OUT + (size_t)b * L_TOTAL;

    // ---------------- stream state ----------------
    int   fb_[2], gg_[2];
    float env[2], hh[2];
    float d0[2], d1[2], d2[2], d3[2], d4[2], d5[2], d6[2], d7[2];
    float s11[2], s12[2], s21[2], s22[2], s31[2], s32[2], s41[2], s42[2], sf1[2], sf2[2];

#pragma unroll
    for (int k = 0; k < 2; k++) {
        const int c = cp + k * NPAIR;
        fb_[k] = c * CHUNK - FWARM;                 // may be negative (zero-padded)
        int g = 3 - fb_[k]; if (g < 3) g = 3;
        gg_[k] = g;
        env[k] = 0.f; hh[k] = 0.f;
        d0[k]=d1[k]=d2[k]=d3[k]=d4[k]=d5[k]=d6[k]=d7[k]=0.f;
        s11[k]=s12[k]=s21[k]=s22[k]=s31[k]=s32[k]=s41[k]=s42[k]=sf1[k]=sf2[k]=0.f;
    }

    // ---------------- exact envelope pre-scan ----------------
    {
        const float cc2 = cenv * cenv, cc4 = cc2 * cc2;
        const float g0 = ccenv * cenv * cc2;
        const float g1 = ccenv * cc2;
        const float g2 = ccenv * cenv;
        const float g3 = ccenv;
#pragma unroll
        for (int k = 0; k < 2; k++) {
            int t0 = fb_[k] - ENVW; if (t0 < 0) t0 = 0;
            float e = 0.f;
            for (int t = t0; t < fb_[k]; t += 4) {
                float4 v = *reinterpret_cast<const float4*>(xr + t);
                float a = g0 * fabsf(v.x);
                a = fmaf(g1, fabsf(v.y), a);
                a = fmaf(g2, fabsf(v.z), a);
                a = fmaf(g3, fabsf(v.w), a);
                e = fmaf(cc4, e, a);
            }
            env[k] = e;
        }
    }

#define PSTEP(G_, k_, xv_, it_) pipe_step<G_>(xv_, it_, gg_[k_], c1, c2, c3, c4, cf, G, \
        cenv, ccenv, depth, fbmix, env[k_], hh[k_], d0[k_], d1[k_], d2[k_], d3[k_],     \
        d4[k_], d5[k_], d6[k_], d7[k_], s11[k_], s12[k_], s21[k_], s22[k_],             \
        s31[k_], s32[k_], s41[k_], s42[k_], sf1[k_], sf2[k_])

    // ---------------- prologue (SKEW scalar iters, select-guarded) ----------------
#pragma unroll
    for (int i = 0; i < SKEW; i++) {
#pragma unroll
        for (int k = 0; k < 2; k++) {
            int s = fb_[k] + i;
            int sa = s < 0 ? 0 : s;
            float xv = xr[sa];
            xv = (s >= 0) ? xv : 0.f;
            (void)PSTEP(true, k, xv, i);
        }
    }

    // ---------------- warm loop (no stores, masked loads, guarded GRU) ----------------
    for (int i = SKEW; i < WSTART; i += 4) {
        float xv4[2][4];
#pragma unroll
        for (int k = 0; k < 2; k++) {
            int s = fb_[k] + i;
            int sa = s < 0 ? 0 : s;                      // groups are 4-aligned: all-in or all-out
            float4 v = *reinterpret_cast<const float4*>(xr + sa);
            float m = (s >= 0) ? 1.f : 0.f;
            xv4[k][0] = v.x * m; xv4[k][1] = v.y * m;
            xv4[k][2] = v.z * m; xv4[k][3] = v.w * m;
        }
#pragma unroll
        for (int j = 0; j < 4; j++)
#pragma unroll
            for (int k = 0; k < 2; k++)
                (void)PSTEP(true, k, xv4[k][j], i + j);
    }

    // ---------------- output loop (unconditional stores, clean body) ----------------
    for (int i = WSTART; i < ITERS; i += 4) {
        float xv4[2][4];
#pragma unroll
        for (int k = 0; k < 2; k++) {
            int s = fb_[k] + i;
            int sa = s > (L_TOTAL - 4) ? (L_TOTAL - 4) : s;  // tail over-read is dead data
            float4 v = *reinterpret_cast<const float4*>(xr + sa);
            xv4[k][0] = v.x; xv4[k][1] = v.y; xv4[k][2] = v.z; xv4[k][3] = v.w;
        }
        float ov4[2][4];
#pragma unroll
        for (int j = 0; j < 4; j++)
#pragma unroll
            for (int k = 0; k < 2; k++)
                ov4[k][j] = PSTEP(false, k, xv4[k][j], i + j);
#pragma unroll
        for (int k = 0; k < 2; k++) {
            int s = fb_[k] + i;
            float4 o; o.x=ov4[k][0]; o.y=ov4[k][1]; o.z=ov4[k][2]; o.w=ov4[k][3];
            *reinterpret_cast<float4*>(orow + (s - SKEW)) = o;
        }
    }
#undef PSTEP
}

extern "C" void kernel_launch(void* const* d_in, const int* in_sizes, int n_in,
                              void* d_out, int out_size)
{
    const float* X     = (const float*)d_in[0];
    const float* knobs = (const float*)d_in[1];
    const float* ecr   = (const float*)d_in[2];
    const float* prep  = (const float*)d_in[3];
    const float* postp = (const float*)d_in[4];
    const float* gwi   = (const float*)d_in[5];
    const float* gwh   = (const float*)d_in[6];
    const float* gbi   = (const float*)d_in[7];
    const float* gbh   = (const float*)d_in[8];
    const float* gow   = (const float*)d_in[9];
    const float* gob   = (const float*)d_in[10];
    const float* sw1   = (const float*)d_in[11];
    const float* sb1   = (const float*)d_in[12];
    const float* sw2   = (const float*)d_in[13];
    const float* sb2   = (const float*)d_in[14];
    const float* fw1   = (const float*)d_in[15];
    const float* fb1   = (const float*)d_in[16];
    const float* fw2   = (const float*)d_in[17];
    const float* fb2   = (const float*)d_in[18];
    const float* famt  = (const float*)d_in[19];
    float* OUT = (float*)d_out;

    dim3 grid(NTHREADS / BLOCK);
    amp_kernel<<<grid, BLOCK>>>(X, knobs, ecr, prep, postp, gwi, gwh, gbi, gbh,
                                gow, gob, sw1, sb1, sw2, sb2, fw1, fb1, fw2, fb2,
                                famt, OUT);
}